// round 7
// baseline (speedup 1.0000x reference)
#include <cuda_runtime.h>
#include <cuda_fp16.h>

#define MAXN 100000
#define MAXE 1600000
#define HIDC 64
#define NB 64

// ---------------- device scratch (BSS zero-initialized; zero-restore discipline) ----------------
__device__ __align__(16) int    g_deg[MAXN];        // zeroed by k_scanA after read
__device__ __align__(16) int    g_off[MAXN + 1];
__device__ __align__(16) int    g_cur[MAXN];
__device__ __align__(16) int    g_srcidx[MAXE];
__device__ __align__(16) int    g_part[128];
__device__ __align__(16) __half2 g_y16a[MAXN * 32];
__device__ __align__(16) __half2 g_y16b[MAXN * 32];
__device__ __align__(16) float  g_agg[MAXN * HIDC];
__device__ __align__(16) float  g_hself[MAXN * HIDC];
__device__ __align__(16) float  g_stats[3 * 2 * HIDC]; // [0..127] zeroed by mm(L2), [128..255] by mm(L3), [256..383] by head
__device__ float g_sumexp;                           // zeroed by head
__device__ __align__(16) float  g_pool[NB * HIDC];   // zeroed by head
__device__ int   g_bcnt[NB];                         // zeroed by head

// ---------------- f32x2 packed math helpers ----------------
__device__ __forceinline__ unsigned long long pack2(float lo, float hi) {
    unsigned long long r;
    asm("mov.b64 %0, {%1, %2};" : "=l"(r) : "f"(lo), "f"(hi));
    return r;
}
__device__ __forceinline__ void fma2(unsigned long long& d, unsigned long long a, unsigned long long b) {
    asm("fma.rn.f32x2 %0, %1, %2, %0;" : "+l"(d) : "l"(a), "l"(b));
}
__device__ __forceinline__ float2 unpack2(unsigned long long v) {
    float lo, hi;
    asm("mov.b64 {%0, %1}, %2;" : "=f"(lo), "=f"(hi) : "l"(v));
    return make_float2(lo, hi);
}

// ---------------- per-block dtype detection ----------------
// If data is int32 pairs, an int64 view v = lo + hi*2^32 with hi = next index;
// v >= 2^32 > n unless hi == 0 (P = 1e-5 per sample). 32 samples -> certain.
__device__ __forceinline__ int block_is64(const long long* __restrict__ ei, int n, int* s_is64) {
    if (threadIdx.x < 32) {
        long long v = ei[threadIdx.x];
        int bad = (v < 0 || v >= (long long)n) ? 1 : 0;
        bad = __any_sync(0xffffffffu, bad);
        if (threadIdx.x == 0) *s_is64 = bad ? 0 : 1;
    }
    __syncthreads();
    return *s_is64;
}
__device__ __forceinline__ int load_idx2(const void* p, int i, int is64) {
    if (is64) return (int)((const long long*)p)[i];
    return ((const int*)p)[i];
}

// ---------------- 1: hist (+ fused prepool: sumexp + batch counts) ----------------
__global__ void k_hist(const void* __restrict__ ei, const float* __restrict__ x,
                       const void* __restrict__ batch, int e, int n) {
    __shared__ float ssum[256];
    __shared__ int hist[64];
    __shared__ int s_is64;
    int is64 = block_is64((const long long*)ei, n, &s_is64);
    int tid = threadIdx.x;
    int i = blockIdx.x * 256 + tid;
    if (i < e) atomicAdd(&g_deg[load_idx2(ei, e + i, is64)], 1);
    if (tid < 64) hist[tid] = 0;
    __syncthreads();
    float loc = 0.f;
    if (i < n) {
        loc = expf(__ldg(&x[i * 6 + 4]));
        atomicAdd(&hist[load_idx2(batch, i, is64)], 1);
    }
    ssum[tid] = loc; __syncthreads();
    for (int d = 128; d > 0; d >>= 1) {
        if (tid < d) ssum[tid] += ssum[tid + d];
        __syncthreads();
    }
    if (tid == 0 && ssum[0] != 0.f) atomicAdd(&g_sumexp, ssum[0]);
    if (tid < 64 && hist[tid]) atomicAdd(&g_bcnt[tid], hist[tid]);
}

// ---------------- 2: scanA (per-block local exclusive scan + block totals; re-zero g_deg) ----------------
__global__ void k_scanA(int n) {
    __shared__ int sh[1024];
    int t = threadIdx.x;
    int i = blockIdx.x * 1024 + t;
    int v = (i < n) ? g_deg[i] : 0;
    sh[t] = v; __syncthreads();
    for (int d = 1; d < 1024; d <<= 1) {
        int add = (t >= d) ? sh[t - d] : 0;
        __syncthreads();
        sh[t] += add;
        __syncthreads();
    }
    int excl = sh[t] - v;
    if (i < n) { g_off[i] = excl; g_cur[i] = excl; g_deg[i] = 0; }
    if (t == 1023) g_part[blockIdx.x] = sh[1023];
}

// ---------------- 3: scatter (smem scan of block totals; scatter; absolutize g_off) ----------------
__global__ void k_scatter(const void* __restrict__ ei, int e, int n, int nb) {
    __shared__ int sp[128];
    __shared__ int s_is64;
    int is64 = block_is64((const long long*)ei, n, &s_is64);
    int tid = threadIdx.x;
    if (tid < 128) sp[tid] = (tid < nb) ? g_part[tid] : 0;
    __syncthreads();
    for (int d = 1; d < 128; d <<= 1) {
        int v = 0;
        if (tid < 128 && tid >= d) v = sp[tid - d];
        __syncthreads();
        if (tid < 128) sp[tid] += v;
        __syncthreads();
    }
    int ex = 0;
    if (tid > 0 && tid < 128) ex = sp[tid - 1];
    __syncthreads();
    if (tid < 128) sp[tid] = ex;
    __syncthreads();

    int i = blockIdx.x * 256 + tid;
    if (i < e) {
        int src = load_idx2(ei, i, is64);
        int dst = load_idx2(ei, e + i, is64);
        int pos = atomicAdd(&g_cur[dst], 1) + sp[dst >> 10];
        g_srcidx[pos] = src;
    }
    if (i < n) g_off[i] += sp[i >> 10];
    if (i == 0) g_off[n] = e;
}

// ---------------- 4: fused layer-1 (agg 6ch + mm + stats, fp16 out)  [PROFILED SLOT] ----------------
__global__ void __launch_bounds__(256)
k_l1(const float* __restrict__ x,
     const float* __restrict__ W1l, const float* __restrict__ W1r,
     const float* __restrict__ b1,
     __half2* __restrict__ yout, float* __restrict__ stats, int n) {
    __shared__ float sWl[6 * 64];
    __shared__ float sWr[6 * 64];
    __shared__ float sb[64];
    __shared__ float redS[8][64];
    __shared__ float redQ[8][64];
    int tid = threadIdx.x;
    for (int i = tid; i < 6 * 64; i += 256) { sWl[i] = W1l[i]; sWr[i] = W1r[i]; }
    if (tid < 64) sb[tid] = b1[tid];
    __syncthreads();

    int warp = tid >> 5, lane = tid & 31, c0 = lane * 2;
    int base = (blockIdx.x * 8 + warp) * 8;
    float ls0 = 0.f, ls1 = 0.f, lq0 = 0.f, lq1 = 0.f;

#pragma unroll 1
    for (int j = 0; j < 8; j++) {
        int node = base + j;
        bool valid = node < n;
        float acc = 0.f, xv = 0.f;
        int deg = 0;
        if (valid) {
            int s = g_off[node], t = g_off[node + 1];
            deg = t - s;
            // predicated MLP-4 gather
            for (int e = s; e < t; e += 4) {
                int idx[4];
#pragma unroll
                for (int u = 0; u < 4; u++) {
                    int ee = e + u;
                    idx[u] = __ldg(&g_srcidx[ee < t ? ee : s]);
                }
#pragma unroll
                for (int u = 0; u < 4; u++) {
                    float a = (lane < 6) ? __ldg(&x[idx[u] * 6 + lane]) : 0.f;
                    if (e + u < t) acc += a;
                }
            }
            if (lane < 6) xv = __ldg(&x[node * 6 + lane]);
        }
        acc *= 1.f / fmaxf((float)deg, 1.f);

        float y0 = sb[c0], y1 = sb[c0 + 1];
#pragma unroll
        for (int k = 0; k < 6; k++) {
            float ak = __shfl_sync(0xffffffffu, acc, k);
            float xk = __shfl_sync(0xffffffffu, xv, k);
            y0 += ak * sWl[k * 64 + c0]     + xk * sWr[k * 64 + c0];
            y1 += ak * sWl[k * 64 + c0 + 1] + xk * sWr[k * 64 + c0 + 1];
        }
        if (valid) {
            yout[node * 32 + lane] = __float22half2_rn(make_float2(y0, y1));
            ls0 += y0; lq0 += y0 * y0;
            ls1 += y1; lq1 += y1 * y1;
        }
    }
    redS[warp][c0] = ls0; redS[warp][c0 + 1] = ls1;
    redQ[warp][c0] = lq0; redQ[warp][c0 + 1] = lq1;
    __syncthreads();
    if (tid < 64) {
        float s = 0.f, q = 0.f;
#pragma unroll
        for (int w2 = 0; w2 < 8; w2++) { s += redS[w2][tid]; q += redQ[w2][tid]; }
        atomicAdd(&stats[tid], s);
        atomicAdd(&stats[64 + tid], q);
    }
}

// ---------------- 5/7: agg64h (fp16 gather + BN-on-read + BN'd self, predicated MLP-8) ----------------
__global__ void k_agg64h(const __half2* __restrict__ yin,
                         const float* __restrict__ stats,
                         const float* __restrict__ gam, const float* __restrict__ bet,
                         float invn,
                         float* __restrict__ aggout, float* __restrict__ hselfout, int n) {
    __shared__ float ssc[64], ssh[64];
    int tid = threadIdx.x;
    if (tid < 64) {
        float mu = stats[tid] * invn;
        float var = stats[64 + tid] * invn - mu * mu;
        float rstd = rsqrtf(var + 1e-5f);
        float sc = rstd * gam[tid];
        ssc[tid] = sc;
        ssh[tid] = bet[tid] - mu * sc;
    }
    __syncthreads();
    int w = (blockIdx.x * blockDim.x + tid) >> 5;
    int lane = tid & 31;
    if (w >= n) return;
    float sc0 = ssc[lane * 2], sc1 = ssc[lane * 2 + 1];
    float sh0 = ssh[lane * 2], sh1 = ssh[lane * 2 + 1];
    int s = g_off[w], t = g_off[w + 1];
    float ax = 0.f, ay = 0.f;
    for (int e = s; e < t; e += 8) {
        int idx[8];
#pragma unroll
        for (int u = 0; u < 8; u++) {
            int ee = e + u;
            idx[u] = __ldg(&g_srcidx[ee < t ? ee : s]);
        }
#pragma unroll
        for (int u = 0; u < 8; u++) {
            float2 f = __half22float2(__ldg(&yin[idx[u] * 32 + lane]));
            float vx = fmaxf(fmaf(f.x, sc0, sh0), 0.f);
            float vy = fmaxf(fmaf(f.y, sc1, sh1), 0.f);
            if (e + u < t) { ax += vx; ay += vy; }
        }
    }
    float inv = 1.f / fmaxf((float)(t - s), 1.f);
    ((float2*)aggout)[w * 32 + lane] = make_float2(ax * inv, ay * inv);
    float2 fs = __half22float2(__ldg(&yin[w * 32 + lane]));
    ((float2*)hselfout)[w * 32 + lane] =
        make_float2(fmaxf(fmaf(fs.x, sc0, sh0), 0.f), fmaxf(fmaf(fs.y, sc1, sh1), 0.f));
}

// ---------------- 6/8: dense matmul (FFMA2) + BN-stats, fp16 output; zeroes prev stats ----------------
__global__ void __launch_bounds__(256)
k_mm(const float* __restrict__ aggin, const float* __restrict__ hin,
     const float* __restrict__ Wl, const float* __restrict__ Wr,
     const float* __restrict__ bias, __half2* __restrict__ yout,
     float* __restrict__ stats, float* __restrict__ zstats, int n) {
    __shared__ float sWl[64 * 64];
    __shared__ float sWr[64 * 64];
    __shared__ float sb[64];
    __shared__ float redS[8][64];
    __shared__ float redQ[8][64];
    int tid = threadIdx.x;
    if (blockIdx.x == 0 && tid < 128 && zstats) zstats[tid] = 0.f;  // restore-zero for next replay
    for (int i = tid; i < 64 * 64; i += 256) {
        int k = i >> 6, c = i & 63;
        int dst = (((k >> 1) << 6) + c) * 2 + (k & 1);
        sWl[dst] = Wl[i]; sWr[dst] = Wr[i];
    }
    if (tid < 64) sb[tid] = bias[tid];
    __syncthreads();

    int warp = tid >> 5, lane = tid & 31;
    int c0 = lane * 2;
    int base = (blockIdx.x * 8 + warp) * 8;

    unsigned long long acc0[8], acc1[8];
#pragma unroll
    for (int j = 0; j < 8; j++) {
        acc0[j] = pack2(sb[c0], 0.f);
        acc1[j] = pack2(sb[c0 + 1], 0.f);
    }
#pragma unroll 4
    for (int k = 0; k < 64; k += 4) {
        float4 wl01 = *(float4*)&sWl[((k >> 1) * 64 + c0) * 2];
        float4 wl23 = *(float4*)&sWl[(((k >> 1) + 1) * 64 + c0) * 2];
        float4 wr01 = *(float4*)&sWr[((k >> 1) * 64 + c0) * 2];
        float4 wr23 = *(float4*)&sWr[(((k >> 1) + 1) * 64 + c0) * 2];
        unsigned long long pl0a = pack2(wl01.x, wl01.y);
        unsigned long long pl0b = pack2(wl01.z, wl01.w);
        unsigned long long pl1a = pack2(wl23.x, wl23.y);
        unsigned long long pl1b = pack2(wl23.z, wl23.w);
        unsigned long long pr0a = pack2(wr01.x, wr01.y);
        unsigned long long pr0b = pack2(wr01.z, wr01.w);
        unsigned long long pr1a = pack2(wr23.x, wr23.y);
        unsigned long long pr1b = pack2(wr23.z, wr23.w);
#pragma unroll
        for (int j = 0; j < 8; j++) {
            int node = base + j; if (node >= n) node = n - 1;
            float4 a = *(const float4*)&aggin[node * 64 + k];
            float4 h = *(const float4*)&hin[node * 64 + k];
            unsigned long long axy = pack2(a.x, a.y);
            unsigned long long azw = pack2(a.z, a.w);
            unsigned long long hxy = pack2(h.x, h.y);
            unsigned long long hzw = pack2(h.z, h.w);
            fma2(acc0[j], axy, pl0a);
            fma2(acc1[j], axy, pl0b);
            fma2(acc0[j], azw, pl1a);
            fma2(acc1[j], azw, pl1b);
            fma2(acc0[j], hxy, pr0a);
            fma2(acc1[j], hxy, pr0b);
            fma2(acc0[j], hzw, pr1a);
            fma2(acc1[j], hzw, pr1b);
        }
    }

    float ls0 = 0.f, ls1 = 0.f, lq0 = 0.f, lq1 = 0.f;
#pragma unroll
    for (int j = 0; j < 8; j++) {
        int node = base + j;
        if (node < n) {
            float2 u0 = unpack2(acc0[j]);
            float2 u1 = unpack2(acc1[j]);
            float v0 = u0.x + u0.y;
            float v1 = u1.x + u1.y;
            yout[node * 32 + lane] = __float22half2_rn(make_float2(v0, v1));
            ls0 += v0; lq0 += v0 * v0;
            ls1 += v1; lq1 += v1 * v1;
        }
    }
    redS[warp][c0] = ls0; redS[warp][c0 + 1] = ls1;
    redQ[warp][c0] = lq0; redQ[warp][c0 + 1] = lq1;
    __syncthreads();
    if (tid < 64) {
        float s = 0.f, q = 0.f;
#pragma unroll
        for (int w2 = 0; w2 < 8; w2++) { s += redS[w2][tid]; q += redQ[w2][tid]; }
        atomicAdd(&stats[tid], s);
        atomicAdd(&stats[64 + tid], q);
    }
}

// ---------------- 9: pooling (BN3 + ReLU on read) ----------------
__global__ void k_pool(const void* __restrict__ batch, const void* __restrict__ ei,
                       const float* __restrict__ x,
                       const __half2* __restrict__ y16,
                       const float* __restrict__ stats,
                       const float* __restrict__ gam, const float* __restrict__ bet,
                       float invn, int n) {
    __shared__ float w[64];
    __shared__ int bb[64];
    __shared__ float2 sscsh[64];
    __shared__ int s_is64;
    int is64 = block_is64((const long long*)ei, n, &s_is64);
    int tid = threadIdx.x;  // 0..31
    int base = blockIdx.x * 64;
    float S = g_sumexp;
    for (int j = tid; j < 64; j += 32) {
        int i = base + j;
        if (i < n) { w[j] = expf(__ldg(&x[i * 6 + 4])) / S; bb[j] = load_idx2(batch, i, is64); }
        else { w[j] = 0.f; bb[j] = -1; }
        float mu = stats[j] * invn;
        float var = stats[64 + j] * invn - mu * mu;
        float rstd = rsqrtf(var + 1e-5f);
        float sc = rstd * gam[j];
        sscsh[j] = make_float2(sc, bet[j] - mu * sc);
    }
    __syncthreads();
    int c0 = tid * 2;
    float2 p0 = sscsh[c0], p1 = sscsh[c0 + 1];
    int m = n - base; if (m > 64) m = 64;
#define BNV(f) make_float2(fmaxf(fmaf((f).x, p0.x, p0.y), 0.f), fmaxf(fmaf((f).y, p1.x, p1.y), 0.f))
    if (m == 64 && bb[0] == bb[63]) {
        float ax0 = 0.f, ay0 = 0.f, ax1 = 0.f, ay1 = 0.f;
        float ax2 = 0.f, ay2 = 0.f, ax3 = 0.f, ay3 = 0.f;
        for (int j = 0; j < 64; j += 4) {
            float2 f0 = BNV(__half22float2(__ldg(&y16[(base + j + 0) * 32 + tid])));
            float2 f1 = BNV(__half22float2(__ldg(&y16[(base + j + 1) * 32 + tid])));
            float2 f2 = BNV(__half22float2(__ldg(&y16[(base + j + 2) * 32 + tid])));
            float2 f3 = BNV(__half22float2(__ldg(&y16[(base + j + 3) * 32 + tid])));
            ax0 += w[j] * f0.x;     ay0 += w[j] * f0.y;
            ax1 += w[j + 1] * f1.x; ay1 += w[j + 1] * f1.y;
            ax2 += w[j + 2] * f2.x; ay2 += w[j + 2] * f2.y;
            ax3 += w[j + 3] * f3.x; ay3 += w[j + 3] * f3.y;
        }
        atomicAdd(&g_pool[bb[0] * 64 + c0],     (ax0 + ax1) + (ax2 + ax3));
        atomicAdd(&g_pool[bb[0] * 64 + c0 + 1], (ay0 + ay1) + (ay2 + ay3));
    } else {
        float accx = 0.f, accy = 0.f;
        int cur = bb[0];
        for (int j = 0; j < m; j++) {
            int b = bb[j];
            if (b != cur) {
                if (cur >= 0) {
                    atomicAdd(&g_pool[cur * 64 + c0], accx);
                    atomicAdd(&g_pool[cur * 64 + c0 + 1], accy);
                }
                accx = 0.f; accy = 0.f; cur = b;
            }
            float2 f = BNV(__half22float2(__ldg(&y16[(base + j) * 32 + tid])));
            accx += w[j] * f.x; accy += w[j] * f.y;
        }
        if (cur >= 0 && m > 0) {
            atomicAdd(&g_pool[cur * 64 + c0], accx);
            atomicAdd(&g_pool[cur * 64 + c0 + 1], accy);
        }
    }
#undef BNV
}

// ---------------- 10: heads (+ restore zeros for next replay) ----------------
__global__ void k_head(const float* __restrict__ phW1, const float* __restrict__ phb1,
                       const float* __restrict__ phW2, const float* __restrict__ phb2,
                       const float* __restrict__ trW1, const float* __restrict__ trb1,
                       const float* __restrict__ trW2, const float* __restrict__ trb2,
                       float* __restrict__ zstats, float* __restrict__ out) {
    __shared__ float pool[64 * 64];
    __shared__ float hid[64 * 32];
    __shared__ float hidt[64 * 16];
    int tid = threadIdx.x;
    for (int i = tid; i < 64 * 64; i += 256) {
        int b = i >> 6;
        float c = (float)g_bcnt[b];
        pool[i] = g_pool[i] / fmaxf(c, 1.f);
    }
    __syncthreads();
    // restore zeros (all reads of these globals are complete)
    for (int i = tid; i < 64 * 64; i += 256) g_pool[i] = 0.f;
    if (tid < 64) g_bcnt[tid] = 0;
    if (tid < 128) zstats[tid] = 0.f;
    if (tid == 0) g_sumexp = 0.f;

    for (int i = tid; i < 64 * 32; i += 256) {
        int b = i >> 5, j = i & 31;
        float s = phb1[j];
        for (int k = 0; k < 64; k++) s += pool[b * 64 + k] * phW1[k * 32 + j];
        hid[i] = fmaxf(s, 0.f);
    }
    for (int i = tid; i < 64 * 16; i += 256) {
        int b = i >> 4, j = i & 15;
        float s = trb1[j];
        for (int k = 0; k < 64; k++) s += pool[b * 64 + k] * trW1[k * 16 + j];
        hidt[i] = fmaxf(s, 0.f);
    }
    __syncthreads();
    for (int i = tid; i < 64 * 3; i += 256) {
        int b = i / 3, j = i - b * 3;
        float s = phb2[j];
        for (int k = 0; k < 32; k++) s += hid[b * 32 + k] * phW2[k * 3 + j];
        out[i] = s;
    }
    for (int i = tid; i < 64; i += 256) {
        float s = trb2[0];
        for (int k = 0; k < 16; k++) s += hidt[i * 16 + k] * trW2[k];
        out[192 + i] = 1.f / (1.f + expf(-s));
    }
}

// ---------------- launch ----------------
extern "C" void kernel_launch(void* const* d_in, const int* in_sizes, int n_in,
                              void* d_out, int out_size) {
    const float* x   = (const float*)d_in[0];
    const void*  ei  = d_in[1];
    const void*  bat = d_in[2];
    const float* W1l = (const float*)d_in[3];
    const float* b1  = (const float*)d_in[4];
    const float* W1r = (const float*)d_in[5];
    const float* W2l = (const float*)d_in[6];
    const float* b2  = (const float*)d_in[7];
    const float* W2r = (const float*)d_in[8];
    const float* W3l = (const float*)d_in[9];
    const float* b3  = (const float*)d_in[10];
    const float* W3r = (const float*)d_in[11];
    const float* g1  = (const float*)d_in[12];
    const float* be1 = (const float*)d_in[13];
    const float* g2  = (const float*)d_in[14];
    const float* be2 = (const float*)d_in[15];
    const float* g3  = (const float*)d_in[16];
    const float* be3 = (const float*)d_in[17];
    const float* phW1 = (const float*)d_in[18];
    const float* phb1 = (const float*)d_in[19];
    const float* phW2 = (const float*)d_in[20];
    const float* phb2 = (const float*)d_in[21];
    const float* trW1 = (const float*)d_in[22];
    const float* trb1 = (const float*)d_in[23];
    const float* trW2 = (const float*)d_in[24];
    const float* trb2 = (const float*)d_in[25];
    float* out = (float*)d_out;

    int n = in_sizes[0] / 6;
    int e = in_sizes[1] / 2;

    float *p_agg, *p_hself, *p_stats;
    __half2 *p_ya, *p_yb;
    cudaGetSymbolAddress((void**)&p_agg, g_agg);
    cudaGetSymbolAddress((void**)&p_hself, g_hself);
    cudaGetSymbolAddress((void**)&p_stats, g_stats);
    cudaGetSymbolAddress((void**)&p_ya, g_y16a);
    cudaGetSymbolAddress((void**)&p_yb, g_y16b);

    int nb = (n + 1023) / 1024;
    int eBlocks = (e + 255) / 256;
    int aggBlocks = (n * 32 + 255) / 256;
    int mmBlocks = (n + 63) / 64;
    float invn = 1.f / (float)n;

    // 1-3: CSR (globals pre-zeroed by previous replay / BSS init)
    k_hist<<<eBlocks, 256>>>(ei, x, bat, e, n);
    k_scanA<<<nb, 1024>>>(n);
    k_scatter<<<eBlocks, 256>>>(ei, e, n, nb);

    // 4: fused layer 1   <- profiled slot
    k_l1<<<mmBlocks, 256>>>(x, W1l, W1r, b1, p_ya, p_stats + 0 * 128, n);

    // 5-6: layer 2 (mm zeroes stats0 for next replay)
    k_agg64h<<<aggBlocks, 256>>>(p_ya, p_stats + 0 * 128, g1, be1, invn, p_agg, p_hself, n);
    k_mm<<<mmBlocks, 256>>>(p_agg, p_hself, W2l, W2r, b2, p_yb, p_stats + 1 * 128, p_stats + 0 * 128, n);

    // 7-8: layer 3 (mm zeroes stats1)
    k_agg64h<<<aggBlocks, 256>>>(p_yb, p_stats + 1 * 128, g2, be2, invn, p_agg, p_hself, n);
    k_mm<<<mmBlocks, 256>>>(p_agg, p_hself, W3l, W3r, b3, p_ya, p_stats + 2 * 128, p_stats + 1 * 128, n);

    // 9-10: pooling + heads (head zeroes pool/bcnt/sumexp/stats2)
    k_pool<<<mmBlocks, 32>>>(bat, ei, x, p_ya, p_stats + 2 * 128, g3, be3, invn, n);
    k_head<<<1, 256>>>(phW1, phb1, phW2, phb2, trW1, trb1, trW2, trb2, p_stats + 2 * 128, out);
}

// round 8
// speedup vs baseline: 1.0649x; 1.0649x over previous
#include <cuda_runtime.h>
#include <cuda_fp16.h>

#define MAXN 100000
#define MAXE 1600000
#define HIDC 64
#define NB 64

// ---------------- device scratch (BSS zeroed; zero-restore discipline) ----------------
__device__ __align__(16) int    g_deg[MAXN];          // re-zeroed by k_scanA
__device__ __align__(16) int    g_off[MAXN + 1];
__device__ __align__(16) int    g_cur[MAXN];
__device__ __align__(16) int    g_srcidx[MAXE];
__device__ __align__(16) int    g_part[128];
__device__ __align__(16) __half2 g_y16a[MAXN * 32];
__device__ __align__(16) __half2 g_y16b[MAXN * 32];
__device__ __align__(16) __half2 g_h16[MAXN * 32];
__device__ __align__(16) float  g_agg[MAXN * HIDC];
__device__ __align__(16) float  g_h32[MAXN * HIDC];
__device__ __align__(16) float  g_stats[3 * 2 * HIDC]; // stats0/1 zeroed by agg64s, stats2 by head
__device__ float g_sumexp;                             // zeroed by head
__device__ __align__(16) float  g_pool[NB * HIDC];     // zeroed by head
__device__ int   g_bcnt[NB];                           // zeroed by head

// ---------------- f32x2 packed math helpers ----------------
__device__ __forceinline__ unsigned long long pack2(float lo, float hi) {
    unsigned long long r;
    asm("mov.b64 %0, {%1, %2};" : "=l"(r) : "f"(lo), "f"(hi));
    return r;
}
__device__ __forceinline__ void fma2(unsigned long long& d, unsigned long long a, unsigned long long b) {
    asm("fma.rn.f32x2 %0, %1, %2, %0;" : "+l"(d) : "l"(a), "l"(b));
}
__device__ __forceinline__ float2 unpack2(unsigned long long v) {
    float lo, hi;
    asm("mov.b64 {%0, %1}, %2;" : "=f"(lo), "=f"(hi) : "l"(v));
    return make_float2(lo, hi);
}

// ---------------- per-block dtype detection ----------------
__device__ __forceinline__ int block_is64(const long long* __restrict__ ei, int n, int* s_is64) {
    if (threadIdx.x < 32) {
        long long v = ei[threadIdx.x];
        int bad = (v < 0 || v >= (long long)n) ? 1 : 0;
        bad = __any_sync(0xffffffffu, bad);
        if (threadIdx.x == 0) *s_is64 = bad ? 0 : 1;
    }
    __syncthreads();
    return *s_is64;
}
__device__ __forceinline__ int load_idx2(const void* p, int i, int is64) {
    if (is64) return (int)((const long long*)p)[i];
    return ((const int*)p)[i];
}

// ---------------- 1: hist (+ fused prepool) ----------------
__global__ void k_hist(const void* __restrict__ ei, const float* __restrict__ x,
                       const void* __restrict__ batch, int e, int n) {
    __shared__ float ssum[256];
    __shared__ int hist[64];
    __shared__ int s_is64;
    int is64 = block_is64((const long long*)ei, n, &s_is64);
    int tid = threadIdx.x;
    int i = blockIdx.x * 256 + tid;
    if (i < e) atomicAdd(&g_deg[load_idx2(ei, e + i, is64)], 1);
    if (tid < 64) hist[tid] = 0;
    __syncthreads();
    float loc = 0.f;
    if (i < n) {
        loc = expf(__ldg(&x[i * 6 + 4]));
        atomicAdd(&hist[load_idx2(batch, i, is64)], 1);
    }
    ssum[tid] = loc; __syncthreads();
    for (int d = 128; d > 0; d >>= 1) {
        if (tid < d) ssum[tid] += ssum[tid + d];
        __syncthreads();
    }
    if (tid == 0 && ssum[0] != 0.f) atomicAdd(&g_sumexp, ssum[0]);
    if (tid < 64 && hist[tid]) atomicAdd(&g_bcnt[tid], hist[tid]);
}

// ---------------- 2: scanA ----------------
__global__ void k_scanA(int n) {
    __shared__ int sh[1024];
    int t = threadIdx.x;
    int i = blockIdx.x * 1024 + t;
    int v = (i < n) ? g_deg[i] : 0;
    sh[t] = v; __syncthreads();
    for (int d = 1; d < 1024; d <<= 1) {
        int add = (t >= d) ? sh[t - d] : 0;
        __syncthreads();
        sh[t] += add;
        __syncthreads();
    }
    int excl = sh[t] - v;
    if (i < n) { g_off[i] = excl; g_cur[i] = excl; g_deg[i] = 0; }
    if (t == 1023) g_part[blockIdx.x] = sh[1023];
}

// ---------------- 3: scatter ----------------
__global__ void k_scatter(const void* __restrict__ ei, int e, int n, int nb) {
    __shared__ int sp[128];
    __shared__ int s_is64;
    int is64 = block_is64((const long long*)ei, n, &s_is64);
    int tid = threadIdx.x;
    if (tid < 128) sp[tid] = (tid < nb) ? g_part[tid] : 0;
    __syncthreads();
    for (int d = 1; d < 128; d <<= 1) {
        int v = 0;
        if (tid < 128 && tid >= d) v = sp[tid - d];
        __syncthreads();
        if (tid < 128) sp[tid] += v;
        __syncthreads();
    }
    int ex = 0;
    if (tid > 0 && tid < 128) ex = sp[tid - 1];
    __syncthreads();
    if (tid < 128) sp[tid] = ex;
    __syncthreads();

    int i = blockIdx.x * 256 + tid;
    if (i < e) {
        int src = load_idx2(ei, i, is64);
        int dst = load_idx2(ei, e + i, is64);
        int pos = atomicAdd(&g_cur[dst], 1) + sp[dst >> 10];
        g_srcidx[pos] = src;
    }
    if (i < n) g_off[i] += sp[i >> 10];
    if (i == 0) g_off[n] = e;
}

// ---------------- 4: fused layer-1, edge-per-lane gather  [PROFILED SLOT] ----------------
__global__ void __launch_bounds__(256)
k_l1(const float* __restrict__ x,
     const float* __restrict__ W1l, const float* __restrict__ W1r,
     const float* __restrict__ b1,
     __half2* __restrict__ yout, float* __restrict__ stats, int n) {
    __shared__ float sWl[6 * 64];
    __shared__ float sWr[6 * 64];
    __shared__ float sb[64];
    __shared__ float redS[8][64];
    __shared__ float redQ[8][64];
    int tid = threadIdx.x;
    for (int i = tid; i < 6 * 64; i += 256) { sWl[i] = W1l[i]; sWr[i] = W1r[i]; }
    if (tid < 64) sb[tid] = b1[tid];
    __syncthreads();

    int warp = tid >> 5, lane = tid & 31, c0 = lane * 2;
    int base = (blockIdx.x * 8 + warp) * 8;
    float ls0 = 0.f, ls1 = 0.f, lq0 = 0.f, lq1 = 0.f;

#pragma unroll 1
    for (int j = 0; j < 8; j++) {
        int node = base + j;           // uniform across warp
        bool valid = node < n;
        float a0 = 0.f, a1 = 0.f, a2 = 0.f, a3 = 0.f, a4 = 0.f, a5 = 0.f;
        float s0 = 0.f, s1 = 0.f, s2 = 0.f, s3 = 0.f, s4 = 0.f, s5 = 0.f;
        int deg = 0;
        if (valid) {
            int s = g_off[node], t = g_off[node + 1];
            deg = t - s;
            for (int e = s + lane; e < t; e += 32) {
                int idx = __ldg(&g_srcidx[e]);
                const float2* xp = (const float2*)(x + idx * 6);
                float2 v0 = __ldg(xp);
                float2 v1 = __ldg(xp + 1);
                float2 v2 = __ldg(xp + 2);
                a0 += v0.x; a1 += v0.y; a2 += v1.x;
                a3 += v1.y; a4 += v2.x; a5 += v2.y;
            }
            const float2* xs = (const float2*)(x + node * 6);
            float2 u0 = __ldg(xs), u1 = __ldg(xs + 1), u2 = __ldg(xs + 2);
            s0 = u0.x; s1 = u0.y; s2 = u1.x; s3 = u1.y; s4 = u2.x; s5 = u2.y;
        }
        // butterfly: all lanes end with the full sum (valid is warp-uniform)
#pragma unroll
        for (int d = 16; d > 0; d >>= 1) {
            a0 += __shfl_xor_sync(0xffffffffu, a0, d);
            a1 += __shfl_xor_sync(0xffffffffu, a1, d);
            a2 += __shfl_xor_sync(0xffffffffu, a2, d);
            a3 += __shfl_xor_sync(0xffffffffu, a3, d);
            a4 += __shfl_xor_sync(0xffffffffu, a4, d);
            a5 += __shfl_xor_sync(0xffffffffu, a5, d);
        }
        float inv = 1.f / fmaxf((float)deg, 1.f);
        a0 *= inv; a1 *= inv; a2 *= inv; a3 *= inv; a4 *= inv; a5 *= inv;

        float y0 = sb[c0], y1 = sb[c0 + 1];
        y0 += a0 * sWl[0 * 64 + c0] + s0 * sWr[0 * 64 + c0];
        y1 += a0 * sWl[0 * 64 + c0 + 1] + s0 * sWr[0 * 64 + c0 + 1];
        y0 += a1 * sWl[1 * 64 + c0] + s1 * sWr[1 * 64 + c0];
        y1 += a1 * sWl[1 * 64 + c0 + 1] + s1 * sWr[1 * 64 + c0 + 1];
        y0 += a2 * sWl[2 * 64 + c0] + s2 * sWr[2 * 64 + c0];
        y1 += a2 * sWl[2 * 64 + c0 + 1] + s2 * sWr[2 * 64 + c0 + 1];
        y0 += a3 * sWl[3 * 64 + c0] + s3 * sWr[3 * 64 + c0];
        y1 += a3 * sWl[3 * 64 + c0 + 1] + s3 * sWr[3 * 64 + c0 + 1];
        y0 += a4 * sWl[4 * 64 + c0] + s4 * sWr[4 * 64 + c0];
        y1 += a4 * sWl[4 * 64 + c0 + 1] + s4 * sWr[4 * 64 + c0 + 1];
        y0 += a5 * sWl[5 * 64 + c0] + s5 * sWr[5 * 64 + c0];
        y1 += a5 * sWl[5 * 64 + c0 + 1] + s5 * sWr[5 * 64 + c0 + 1];

        if (valid) {
            yout[node * 32 + lane] = __float22half2_rn(make_float2(y0, y1));
            ls0 += y0; lq0 += y0 * y0;
            ls1 += y1; lq1 += y1 * y1;
        }
    }
    redS[warp][c0] = ls0; redS[warp][c0 + 1] = ls1;
    redQ[warp][c0] = lq0; redQ[warp][c0 + 1] = lq1;
    __syncthreads();
    if (tid < 64) {
        float s = 0.f, q = 0.f;
#pragma unroll
        for (int w2 = 0; w2 < 8; w2++) { s += redS[w2][tid]; q += redQ[w2][tid]; }
        atomicAdd(&stats[tid], s);
        atomicAdd(&stats[64 + tid], q);
    }
}

// ---------------- 5/8: bnh — materialize h = ReLU(BN(y)) as fp16 + fp32 ----------------
__global__ void k_bnh(const __half2* __restrict__ yin, const float* __restrict__ stats,
                      const float* __restrict__ gam, const float* __restrict__ bet,
                      float invn,
                      __half2* __restrict__ h16, float2* __restrict__ h32, int n32) {
    __shared__ float2 sp[64];
    int tid = threadIdx.x;
    if (tid < 64) {
        float mu = stats[tid] * invn;
        float var = stats[64 + tid] * invn - mu * mu;
        float rstd = rsqrtf(var + 1e-5f);
        float sc = rstd * gam[tid];
        sp[tid] = make_float2(sc, bet[tid] - mu * sc);
    }
    __syncthreads();
    int i = blockIdx.x * 256 + tid;
    if (i >= n32) return;
    int c2 = (i & 31) * 2;
    float2 p0 = sp[c2], p1 = sp[c2 + 1];
    float2 f = __half22float2(yin[i]);
    float vx = fmaxf(fmaf(f.x, p0.x, p0.y), 0.f);
    float vy = fmaxf(fmaf(f.y, p1.x, p1.y), 0.f);
    h16[i] = __float22half2_rn(make_float2(vx, vy));
    h32[i] = make_float2(vx, vy);
}

// ---------------- 6/9: agg64s — plain fp16 gather + mean (no BN in loop) ----------------
__global__ void k_agg64s(const __half2* __restrict__ h,
                         float* __restrict__ aggout, float* __restrict__ zstats, int n) {
    if (blockIdx.x == 0 && threadIdx.x < 128 && zstats) zstats[threadIdx.x] = 0.f;
    int w = (blockIdx.x * blockDim.x + threadIdx.x) >> 5;
    int lane = threadIdx.x & 31;
    if (w >= n) return;
    int s = g_off[w], t = g_off[w + 1];
    float ax = 0.f, ay = 0.f;
    int e = s;
    for (; e + 8 <= t; e += 8) {
        int i0 = __ldg(&g_srcidx[e]);
        int i1 = __ldg(&g_srcidx[e + 1]);
        int i2 = __ldg(&g_srcidx[e + 2]);
        int i3 = __ldg(&g_srcidx[e + 3]);
        int i4 = __ldg(&g_srcidx[e + 4]);
        int i5 = __ldg(&g_srcidx[e + 5]);
        int i6 = __ldg(&g_srcidx[e + 6]);
        int i7 = __ldg(&g_srcidx[e + 7]);
        float2 f0 = __half22float2(__ldg(&h[i0 * 32 + lane]));
        float2 f1 = __half22float2(__ldg(&h[i1 * 32 + lane]));
        float2 f2 = __half22float2(__ldg(&h[i2 * 32 + lane]));
        float2 f3 = __half22float2(__ldg(&h[i3 * 32 + lane]));
        float2 f4 = __half22float2(__ldg(&h[i4 * 32 + lane]));
        float2 f5 = __half22float2(__ldg(&h[i5 * 32 + lane]));
        float2 f6 = __half22float2(__ldg(&h[i6 * 32 + lane]));
        float2 f7 = __half22float2(__ldg(&h[i7 * 32 + lane]));
        ax += ((f0.x + f1.x) + (f2.x + f3.x)) + ((f4.x + f5.x) + (f6.x + f7.x));
        ay += ((f0.y + f1.y) + (f2.y + f3.y)) + ((f4.y + f5.y) + (f6.y + f7.y));
    }
    for (; e < t; e++) {
        int i0 = __ldg(&g_srcidx[e]);
        float2 f = __half22float2(__ldg(&h[i0 * 32 + lane]));
        ax += f.x; ay += f.y;
    }
    float inv = 1.f / fmaxf((float)(t - s), 1.f);
    ((float2*)aggout)[w * 32 + lane] = make_float2(ax * inv, ay * inv);
}

// ---------------- 7/10: dense matmul (FFMA2) + BN-stats, fp16 out ----------------
__global__ void __launch_bounds__(256)
k_mm(const float* __restrict__ aggin, const float* __restrict__ hin,
     const float* __restrict__ Wl, const float* __restrict__ Wr,
     const float* __restrict__ bias, __half2* __restrict__ yout,
     float* __restrict__ stats, int n) {
    __shared__ float sWl[64 * 64];
    __shared__ float sWr[64 * 64];
    __shared__ float sb[64];
    __shared__ float redS[8][64];
    __shared__ float redQ[8][64];
    int tid = threadIdx.x;
    for (int i = tid; i < 64 * 64; i += 256) {
        int k = i >> 6, c = i & 63;
        int dst = (((k >> 1) << 6) + c) * 2 + (k & 1);
        sWl[dst] = Wl[i]; sWr[dst] = Wr[i];
    }
    if (tid < 64) sb[tid] = bias[tid];
    __syncthreads();

    int warp = tid >> 5, lane = tid & 31;
    int c0 = lane * 2;
    int base = (blockIdx.x * 8 + warp) * 8;

    unsigned long long acc0[8], acc1[8];
#pragma unroll
    for (int j = 0; j < 8; j++) {
        acc0[j] = pack2(sb[c0], 0.f);
        acc1[j] = pack2(sb[c0 + 1], 0.f);
    }
#pragma unroll 4
    for (int k = 0; k < 64; k += 4) {
        float4 wl01 = *(float4*)&sWl[((k >> 1) * 64 + c0) * 2];
        float4 wl23 = *(float4*)&sWl[(((k >> 1) + 1) * 64 + c0) * 2];
        float4 wr01 = *(float4*)&sWr[((k >> 1) * 64 + c0) * 2];
        float4 wr23 = *(float4*)&sWr[(((k >> 1) + 1) * 64 + c0) * 2];
        unsigned long long pl0a = pack2(wl01.x, wl01.y);
        unsigned long long pl0b = pack2(wl01.z, wl01.w);
        unsigned long long pl1a = pack2(wl23.x, wl23.y);
        unsigned long long pl1b = pack2(wl23.z, wl23.w);
        unsigned long long pr0a = pack2(wr01.x, wr01.y);
        unsigned long long pr0b = pack2(wr01.z, wr01.w);
        unsigned long long pr1a = pack2(wr23.x, wr23.y);
        unsigned long long pr1b = pack2(wr23.z, wr23.w);
#pragma unroll
        for (int j = 0; j < 8; j++) {
            int node = base + j; if (node >= n) node = n - 1;
            float4 a = *(const float4*)&aggin[node * 64 + k];
            float4 h = *(const float4*)&hin[node * 64 + k];
            unsigned long long axy = pack2(a.x, a.y);
            unsigned long long azw = pack2(a.z, a.w);
            unsigned long long hxy = pack2(h.x, h.y);
            unsigned long long hzw = pack2(h.z, h.w);
            fma2(acc0[j], axy, pl0a);
            fma2(acc1[j], axy, pl0b);
            fma2(acc0[j], azw, pl1a);
            fma2(acc1[j], azw, pl1b);
            fma2(acc0[j], hxy, pr0a);
            fma2(acc1[j], hxy, pr0b);
            fma2(acc0[j], hzw, pr1a);
            fma2(acc1[j], hzw, pr1b);
        }
    }

    float ls0 = 0.f, ls1 = 0.f, lq0 = 0.f, lq1 = 0.f;
#pragma unroll
    for (int j = 0; j < 8; j++) {
        int node = base + j;
        if (node < n) {
            float2 u0 = unpack2(acc0[j]);
            float2 u1 = unpack2(acc1[j]);
            float v0 = u0.x + u0.y;
            float v1 = u1.x + u1.y;
            yout[node * 32 + lane] = __float22half2_rn(make_float2(v0, v1));
            ls0 += v0; lq0 += v0 * v0;
            ls1 += v1; lq1 += v1 * v1;
        }
    }
    redS[warp][c0] = ls0; redS[warp][c0 + 1] = ls1;
    redQ[warp][c0] = lq0; redQ[warp][c0 + 1] = lq1;
    __syncthreads();
    if (tid < 64) {
        float s = 0.f, q = 0.f;
#pragma unroll
        for (int w2 = 0; w2 < 8; w2++) { s += redS[w2][tid]; q += redQ[w2][tid]; }
        atomicAdd(&stats[tid], s);
        atomicAdd(&stats[64 + tid], q);
    }
}

// ---------------- 11: pooling (BN3 + ReLU on read) ----------------
__global__ void k_pool(const void* __restrict__ batch, const void* __restrict__ ei,
                       const float* __restrict__ x,
                       const __half2* __restrict__ y16,
                       const float* __restrict__ stats,
                       const float* __restrict__ gam, const float* __restrict__ bet,
                       float invn, int n) {
    __shared__ float w[64];
    __shared__ int bb[64];
    __shared__ float2 sscsh[64];
    __shared__ int s_is64;
    int is64 = block_is64((const long long*)ei, n, &s_is64);
    int tid = threadIdx.x;  // 0..31
    int base = blockIdx.x * 64;
    float S = g_sumexp;
    for (int j = tid; j < 64; j += 32) {
        int i = base + j;
        if (i < n) { w[j] = expf(__ldg(&x[i * 6 + 4])) / S; bb[j] = load_idx2(batch, i, is64); }
        else { w[j] = 0.f; bb[j] = -1; }
        float mu = stats[j] * invn;
        float var = stats[64 + j] * invn - mu * mu;
        float rstd = rsqrtf(var + 1e-5f);
        float sc = rstd * gam[j];
        sscsh[j] = make_float2(sc, bet[j] - mu * sc);
    }
    __syncthreads();
    int c0 = tid * 2;
    float2 p0 = sscsh[c0], p1 = sscsh[c0 + 1];
    int m = n - base; if (m > 64) m = 64;
#define BNV(f) make_float2(fmaxf(fmaf((f).x, p0.x, p0.y), 0.f), fmaxf(fmaf((f).y, p1.x, p1.y), 0.f))
    if (m == 64 && bb[0] == bb[63]) {
        float ax0 = 0.f, ay0 = 0.f, ax1 = 0.f, ay1 = 0.f;
        float ax2 = 0.f, ay2 = 0.f, ax3 = 0.f, ay3 = 0.f;
        for (int j = 0; j < 64; j += 4) {
            float2 f0 = BNV(__half22float2(__ldg(&y16[(base + j + 0) * 32 + tid])));
            float2 f1 = BNV(__half22float2(__ldg(&y16[(base + j + 1) * 32 + tid])));
            float2 f2 = BNV(__half22float2(__ldg(&y16[(base + j + 2) * 32 + tid])));
            float2 f3 = BNV(__half22float2(__ldg(&y16[(base + j + 3) * 32 + tid])));
            ax0 += w[j] * f0.x;     ay0 += w[j] * f0.y;
            ax1 += w[j + 1] * f1.x; ay1 += w[j + 1] * f1.y;
            ax2 += w[j + 2] * f2.x; ay2 += w[j + 2] * f2.y;
            ax3 += w[j + 3] * f3.x; ay3 += w[j + 3] * f3.y;
        }
        atomicAdd(&g_pool[bb[0] * 64 + c0],     (ax0 + ax1) + (ax2 + ax3));
        atomicAdd(&g_pool[bb[0] * 64 + c0 + 1], (ay0 + ay1) + (ay2 + ay3));
    } else {
        float accx = 0.f, accy = 0.f;
        int cur = bb[0];
        for (int j = 0; j < m; j++) {
            int b = bb[j];
            if (b != cur) {
                if (cur >= 0) {
                    atomicAdd(&g_pool[cur * 64 + c0], accx);
                    atomicAdd(&g_pool[cur * 64 + c0 + 1], accy);
                }
                accx = 0.f; accy = 0.f; cur = b;
            }
            float2 f = BNV(__half22float2(__ldg(&y16[(base + j) * 32 + tid])));
            accx += w[j] * f.x; accy += w[j] * f.y;
        }
        if (cur >= 0 && m > 0) {
            atomicAdd(&g_pool[cur * 64 + c0], accx);
            atomicAdd(&g_pool[cur * 64 + c0 + 1], accy);
        }
    }
#undef BNV
}

// ---------------- 12: heads (+ restore zeros) ----------------
__global__ void k_head(const float* __restrict__ phW1, const float* __restrict__ phb1,
                       const float* __restrict__ phW2, const float* __restrict__ phb2,
                       const float* __restrict__ trW1, const float* __restrict__ trb1,
                       const float* __restrict__ trW2, const float* __restrict__ trb2,
                       float* __restrict__ zstats, float* __restrict__ out) {
    __shared__ float pool[64 * 64];
    __shared__ float hid[64 * 32];
    __shared__ float hidt[64 * 16];
    int tid = threadIdx.x;
    for (int i = tid; i < 64 * 64; i += 256) {
        int b = i >> 6;
        float c = (float)g_bcnt[b];
        pool[i] = g_pool[i] / fmaxf(c, 1.f);
    }
    __syncthreads();
    for (int i = tid; i < 64 * 64; i += 256) g_pool[i] = 0.f;
    if (tid < 64) g_bcnt[tid] = 0;
    if (tid < 128) zstats[tid] = 0.f;
    if (tid == 0) g_sumexp = 0.f;

    for (int i = tid; i < 64 * 32; i += 256) {
        int b = i >> 5, j = i & 31;
        float s = phb1[j];
        for (int k = 0; k < 64; k++) s += pool[b * 64 + k] * phW1[k * 32 + j];
        hid[i] = fmaxf(s, 0.f);
    }
    for (int i = tid; i < 64 * 16; i += 256) {
        int b = i >> 4, j = i & 15;
        float s = trb1[j];
        for (int k = 0; k < 64; k++) s += pool[b * 64 + k] * trW1[k * 16 + j];
        hidt[i] = fmaxf(s, 0.f);
    }
    __syncthreads();
    for (int i = tid; i < 64 * 3; i += 256) {
        int b = i / 3, j = i - b * 3;
        float s = phb2[j];
        for (int k = 0; k < 32; k++) s += hid[b * 32 + k] * phW2[k * 3 + j];
        out[i] = s;
    }
    for (int i = tid; i < 64; i += 256) {
        float s = trb2[0];
        for (int k = 0; k < 16; k++) s += hidt[i * 16 + k] * trW2[k];
        out[192 + i] = 1.f / (1.f + expf(-s));
    }
}

// ---------------- launch ----------------
extern "C" void kernel_launch(void* const* d_in, const int* in_sizes, int n_in,
                              void* d_out, int out_size) {
    const float* x   = (const float*)d_in[0];
    const void*  ei  = d_in[1];
    const void*  bat = d_in[2];
    const float* W1l = (const float*)d_in[3];
    const float* b1  = (const float*)d_in[4];
    const float* W1r = (const float*)d_in[5];
    const float* W2l = (const float*)d_in[6];
    const float* b2  = (const float*)d_in[7];
    const float* W2r = (const float*)d_in[8];
    const float* W3l = (const float*)d_in[9];
    const float* b3  = (const float*)d_in[10];
    const float* W3r = (const float*)d_in[11];
    const float* g1  = (const float*)d_in[12];
    const float* be1 = (const float*)d_in[13];
    const float* g2  = (const float*)d_in[14];
    const float* be2 = (const float*)d_in[15];
    const float* g3  = (const float*)d_in[16];
    const float* be3 = (const float*)d_in[17];
    const float* phW1 = (const float*)d_in[18];
    const float* phb1 = (const float*)d_in[19];
    const float* phW2 = (const float*)d_in[20];
    const float* phb2 = (const float*)d_in[21];
    const float* trW1 = (const float*)d_in[22];
    const float* trb1 = (const float*)d_in[23];
    const float* trW2 = (const float*)d_in[24];
    const float* trb2 = (const float*)d_in[25];
    float* out = (float*)d_out;

    int n = in_sizes[0] / 6;
    int e = in_sizes[1] / 2;

    float *p_agg, *p_h32, *p_stats;
    __half2 *p_ya, *p_yb, *p_h16;
    cudaGetSymbolAddress((void**)&p_agg, g_agg);
    cudaGetSymbolAddress((void**)&p_h32, g_h32);
    cudaGetSymbolAddress((void**)&p_stats, g_stats);
    cudaGetSymbolAddress((void**)&p_ya, g_y16a);
    cudaGetSymbolAddress((void**)&p_yb, g_y16b);
    cudaGetSymbolAddress((void**)&p_h16, g_h16);

    int nb = (n + 1023) / 1024;
    int eBlocks = (e + 255) / 256;
    int aggBlocks = (n * 32 + 255) / 256;
    int mmBlocks = (n + 63) / 64;
    int bnBlocks = (n * 32 + 255) / 256;
    float invn = 1.f / (float)n;

    // 1-3: CSR
    k_hist<<<eBlocks, 256>>>(ei, x, bat, e, n);
    k_scanA<<<nb, 1024>>>(n);
    k_scatter<<<eBlocks, 256>>>(ei, e, n, nb);

    // 4: fused layer 1 (profiled)
    k_l1<<<mmBlocks, 256>>>(x, W1l, W1r, b1, p_ya, p_stats + 0 * 128, n);

    // 5-7: layer 2
    k_bnh<<<bnBlocks, 256>>>(p_ya, p_stats + 0 * 128, g1, be1, invn, p_h16, (float2*)p_h32, n * 32);
    k_agg64s<<<aggBlocks, 256>>>(p_h16, p_agg, p_stats + 0 * 128, n);
    k_mm<<<mmBlocks, 256>>>(p_agg, p_h32, W2l, W2r, b2, p_yb, p_stats + 1 * 128, n);

    // 8-10: layer 3
    k_bnh<<<bnBlocks, 256>>>(p_yb, p_stats + 1 * 128, g2, be2, invn, p_h16, (float2*)p_h32, n * 32);
    k_agg64s<<<aggBlocks, 256>>>(p_h16, p_agg, p_stats + 1 * 128, n);
    k_mm<<<mmBlocks, 256>>>(p_agg, p_h32, W3l, W3r, b3, p_ya, p_stats + 2 * 128, n);

    // 11-12: pooling + heads
    k_pool<<<mmBlocks, 32>>>(bat, ei, x, p_ya, p_stats + 2 * 128, g3, be3, invn, n);
    k_head<<<1, 256>>>(phW1, phb1, phW2, phb2, trW1, trb1, trW2, trb2, p_stats + 2 * 128, out);
}